// round 13
// baseline (speedup 1.0000x reference)
#include <cuda_runtime.h>
#include <cstdint>
#include <math.h>

#define BATCH 2048
#define TT 64
#define EE 256
#define SCALE 0.125f
#define FK  16384
#define SPLITK 9            // uneven: 8 x 1824 + 1 x 1792

// ------------------------------------------------------------------
// scratch (static __device__ — no allocations allowed)
// ------------------------------------------------------------------
__device__ float g_x[BATCH * TT * EE];              // attn + query (134MB)
__device__ float g_partial[SPLITK * BATCH * 256];   // 18.9MB

// ------------------------------------------------------------------
// helpers
// ------------------------------------------------------------------
__device__ __forceinline__ void ffma2(uint64_t& d, uint64_t a, uint64_t b) {
    asm("fma.rn.f32x2 %0, %1, %2, %0;" : "+l"(d) : "l"(a), "l"(b));
}
__device__ __forceinline__ uint64_t dupf(float x) {
    uint64_t d; asm("mov.b64 %0, {%1, %1};" : "=l"(d) : "f"(x)); return d;
}
__device__ __forceinline__ void unpack2(uint64_t d, float& lo, float& hi) {
    asm("mov.b64 {%0, %1}, %2;" : "=f"(lo), "=f"(hi) : "l"(d));
}
__device__ __forceinline__ uint32_t smem_u32(const void* p) {
    uint32_t a;
    asm("{ .reg .u64 t; cvta.to.shared.u64 t, %1; cvt.u32.u64 %0, t; }" : "=r"(a) : "l"(p));
    return a;
}
__device__ __forceinline__ float to_tf32(float x) {
    uint32_t u; asm("cvt.rna.tf32.f32 %0, %1;" : "=r"(u) : "f"(x));
    return __uint_as_float(u);
}
__device__ __forceinline__ void mma_tf32(float* c, const uint32_t* a, const uint32_t* b) {
    asm volatile(
        "mma.sync.aligned.m16n8k8.row.col.f32.tf32.tf32.f32 "
        "{%0,%1,%2,%3}, {%4,%5,%6,%7}, {%8,%9}, {%0,%1,%2,%3};"
        : "+f"(c[0]), "+f"(c[1]), "+f"(c[2]), "+f"(c[3])
        : "r"(a[0]), "r"(a[1]), "r"(a[2]), "r"(a[3]), "r"(b[0]), "r"(b[1]));
}
#define CP_ASYNC16(dst, src) \
    asm volatile("cp.async.cg.shared.global [%0], [%1], 16;" :: "r"(dst), "l"(src) : "memory")
#define CP_COMMIT() \
    asm volatile("cp.async.commit_group;" ::: "memory")
#define CP_WAIT(n) \
    asm volatile("cp.async.wait_group %0;" :: "n"(n) : "memory")

// ------------------------------------------------------------------
// attention kernel: 256 threads, 2 CTAs/SM. (R10 version — best measured)
// ------------------------------------------------------------------
#define EC 64
#define NEC 4
#define KC 16
#define NKC 4
#define S_PITCH 65

#define OFF_QT 0
#define OFF_KT 8192
#define OFF_SS 16384
#define OFF_V  0
#define ATTN_SMEM_BYTES ((16384 + 4160) * 4)

__device__ __forceinline__ int qsw(int el, int q) {
    return el * 64 + ((((q) >> 2) ^ (el & 15)) << 2) + (q & 3);
}

__global__ __launch_bounds__(256, 2)
void attn_kernel(const float* __restrict__ Qg, const float* __restrict__ Kg,
                 const float* __restrict__ Vg, float* __restrict__ Ag)
{
    extern __shared__ float sm[];
    float* QT = sm + OFF_QT;
    float* KT = sm + OFF_KT;
    float* Ss = sm + OFF_SS;
    float* Vc = sm + OFF_V;

    const int tid = threadIdx.x;
    const int b   = blockIdx.x;
    const size_t base = (size_t)b * TT * EE;
    const float* qb = Qg + base;
    const float* kb = Kg + base;
    const float* vb = Vg + base;

    const int el = tid & 63;
    const int h  = tid >> 6;
    const int tx = tid & 15;
    const int ty = tid >> 4;

    {
        const float* qsrc = qb + (h * 16) * EE + el;
        const float* ksrc = kb + (h * 16) * EE + el;
        float qs[16], ks[16];
        #pragma unroll
        for (int r = 0; r < 16; ++r) {
            qs[r] = qsrc[r * EE];
            ks[r] = ksrc[r * EE];
        }
        #pragma unroll
        for (int r = 0; r < 16; ++r) {
            const int q = h * 16 + r;
            QT[qsw(el, q)] = qs[r];
            KT[qsw(el, q)] = ks[r];
        }
    }

    uint64_t accS[4][2];
    #pragma unroll
    for (int i = 0; i < 4; ++i) { accS[i][0] = 0ull; accS[i][1] = 0ull; }

    int cur = 0;
    float qs[16], ks[16];
    for (int ec = 0; ec < NEC; ++ec) {
        __syncthreads();
        if (ec < NEC - 1) {
            const float* qsrc = qb + (h * 16) * EE + (ec + 1) * EC + el;
            const float* ksrc = kb + (h * 16) * EE + (ec + 1) * EC + el;
            #pragma unroll
            for (int r = 0; r < 16; ++r) {
                qs[r] = qsrc[r * EE];
                ks[r] = ksrc[r * EE];
            }
        }
        const float* Qb = QT + cur * 4096;
        const float* Kb = KT + cur * 4096;
        #pragma unroll 16
        for (int e = 0; e < EC; ++e) {      // swizzle folds to immediates
            const int sw = e & 15;
            float4 qv = *(const float4*)&Qb[e * 64 + ((ty ^ sw) << 2)];
            float4 kv = *(const float4*)&Kb[e * 64 + ((tx ^ sw) << 2)];
            const uint64_t* kp = (const uint64_t*)&kv;
            ffma2(accS[0][0], dupf(qv.x), kp[0]);
            ffma2(accS[0][1], dupf(qv.x), kp[1]);
            ffma2(accS[1][0], dupf(qv.y), kp[0]);
            ffma2(accS[1][1], dupf(qv.y), kp[1]);
            ffma2(accS[2][0], dupf(qv.z), kp[0]);
            ffma2(accS[2][1], dupf(qv.z), kp[1]);
            ffma2(accS[3][0], dupf(qv.w), kp[0]);
            ffma2(accS[3][1], dupf(qv.w), kp[1]);
        }
        if (ec < NEC - 1) {
            float* Qn = QT + (cur ^ 1) * 4096;
            float* Kn = KT + (cur ^ 1) * 4096;
            #pragma unroll
            for (int r = 0; r < 16; ++r) {
                const int q = h * 16 + r;
                Qn[qsw(el, q)] = qs[r];
                Kn[qsw(el, q)] = ks[r];
            }
            cur ^= 1;
        }
    }

    #pragma unroll
    for (int i = 0; i < 4; ++i) {
        float s0, s1, s2, s3;
        unpack2(accS[i][0], s0, s1);
        unpack2(accS[i][1], s2, s3);
        float* sr = &Ss[(ty * 4 + i) * S_PITCH + tx * 4];
        sr[0] = s0; sr[1] = s1; sr[2] = s2; sr[3] = s3;
    }
    __syncthreads();

    const uint32_t vsm = smem_u32(Vc);
    #pragma unroll
    for (int j = 0; j < 4; ++j) {
        const int f4 = j * 256 + tid;
        CP_ASYNC16(vsm + f4 * 16, (const float4*)vb + f4);
    }
    CP_COMMIT();

    const int warp = tid >> 5, lane = tid & 31;
    #pragma unroll
    for (int rr = 0; rr < 8; ++rr) {
        const int r = warp * 8 + rr;
        float v1 = Ss[r * S_PITCH + lane]      * SCALE;
        float v2 = Ss[r * S_PITCH + lane + 32] * SCALE;
        float m = fmaxf(v1, v2);
        #pragma unroll
        for (int o = 16; o > 0; o >>= 1)
            m = fmaxf(m, __shfl_xor_sync(0xffffffffu, m, o));
        float e1 = expf(v1 - m);
        float e2 = expf(v2 - m);
        float s = e1 + e2;
        #pragma unroll
        for (int o = 16; o > 0; o >>= 1)
            s += __shfl_xor_sync(0xffffffffu, s, o);
        float inv = 1.0f / s;
        Ss[r * S_PITCH + lane]      = e1 * inv;
        Ss[r * S_PITCH + lane + 32] = e2 * inv;
    }

    uint64_t accA[4][4][2];
    #pragma unroll
    for (int i = 0; i < 4; ++i)
        #pragma unroll
        for (int eb = 0; eb < 4; ++eb) { accA[i][eb][0] = 0ull; accA[i][eb][1] = 0ull; }

    for (int kc = 0; kc < NKC; ++kc) {
        if (kc < NKC - 1) {
            const uint32_t dst = vsm + (((kc + 1) & 1) * 4096) * 4;
            #pragma unroll
            for (int j = 0; j < 4; ++j) {
                const int f4 = j * 256 + tid;
                CP_ASYNC16(dst + f4 * 16, (const float4*)vb + (kc + 1) * 1024 + f4);
            }
            CP_COMMIT();
            CP_WAIT(1);
        } else {
            CP_WAIT(0);
        }
        __syncthreads();
        const float* Vb = Vc + (kc & 1) * 4096;
        #pragma unroll 2
        for (int kl = 0; kl < KC; ++kl) {
            const int kg = kc * KC + kl;
            float4 v0 = *(const float4*)&Vb[kl * 256 + tx * 4];
            float4 v1 = *(const float4*)&Vb[kl * 256 + 64 + tx * 4];
            float4 v2 = *(const float4*)&Vb[kl * 256 + 128 + tx * 4];
            float4 v3 = *(const float4*)&Vb[kl * 256 + 192 + tx * 4];
            uint64_t vp[4][2];
            { const uint64_t* u = (const uint64_t*)&v0; vp[0][0] = u[0]; vp[0][1] = u[1]; }
            { const uint64_t* u = (const uint64_t*)&v1; vp[1][0] = u[0]; vp[1][1] = u[1]; }
            { const uint64_t* u = (const uint64_t*)&v2; vp[2][0] = u[0]; vp[2][1] = u[1]; }
            { const uint64_t* u = (const uint64_t*)&v3; vp[3][0] = u[0]; vp[3][1] = u[1]; }
            #pragma unroll
            for (int i = 0; i < 4; ++i) {
                uint64_t sd = dupf(Ss[(ty * 4 + i) * S_PITCH + kg]);
                #pragma unroll
                for (int eb = 0; eb < 4; ++eb) {
                    ffma2(accA[i][eb][0], sd, vp[eb][0]);
                    ffma2(accA[i][eb][1], sd, vp[eb][1]);
                }
            }
        }
        __syncthreads();
    }

    float* ab = Ag + base;
    float* xb = g_x + base;
    #pragma unroll
    for (int i = 0; i < 4; ++i) {
        const int qrow = ty * 4 + i;
        #pragma unroll
        for (int eb = 0; eb < 4; ++eb) {
            const int e0 = eb * 64 + tx * 4;
            float4 o;
            unpack2(accA[i][eb][0], o.x, o.y);
            unpack2(accA[i][eb][1], o.z, o.w);
            float4 q = *(const float4*)&qb[qrow * EE + e0];
            float4 x = make_float4(o.x + q.x, o.y + q.y, o.z + q.z, o.w + q.w);
            *(float4*)&ab[qrow * EE + e0] = o;
            *(float4*)&xb[qrow * EE + e0] = x;
        }
    }
}

// ------------------------------------------------------------------
// FF GEMM via mma.sync tf32 (m16n8k8), fragment-major smem layouts.
// 256 threads = 8 warps, warp grid 4(m) x 2(n): warp tile 32m x 64n.
// BM=128 BN=128 BK=32; reg-staged double buffer; grid (16, 2, 9).
// ------------------------------------------------------------------
#define FBM 128
#define FBN 128
#define FBK 32
#define XW 4096                      // words per X (or W) buffer
#define FF_SMEM_BYTES (4 * XW * 4)   // 64 KB
#define KTPS 57                      // splits 0..7: 57 tiles; split 8: 56

__global__ __launch_bounds__(256, 2)
void ff2_kernel(const float* __restrict__ Wg)
{
    extern __shared__ float fsm[];
    float* Xs = fsm;             // [2][XW] fragment-major A
    float* Ws = fsm + 2 * XW;    // [2][XW] fragment-major B

    const int tid = threadIdx.x;
    const int m0 = blockIdx.x * FBM;
    const int n0 = blockIdx.y * FBN;
    const int z  = blockIdx.z;
    const size_t kbase = (size_t)z * (KTPS * FBK);
    const int ntile = (z == SPLITK - 1) ? 56 : KTPS;

    const int lrow = tid >> 2;          // 0..63
    const int lc   = (tid & 3) * 4;     // 0,4,8,12
    const float* xp0 = g_x + (size_t)(m0 + lrow) * FK + kbase + lc;
    const float* xp1 = g_x + (size_t)(m0 + 64 + lrow) * FK + kbase + lc;
    const float* wp0 = Wg  + (size_t)(n0 + lrow) * FK + kbase + lc;
    const float* wp1 = Wg  + (size_t)(n0 + 64 + lrow) * FK + kbase + lc;

    // precompute STS word indices (depend only on tid)
    // X element (m, kl): ma=m>>4, r=m&15, ks=kl>>3, c=kl&7
    //   idx = ((ma*4+ks)*32 + ((r&7)<<2 | (c&3)))*4 + ((c>>2)<<1 | (r>>3))
    // W element (n, kl): na=n>>3, g=n&7, ks=kl>>3, row=kl&7
    //   idx = (ks*32 + (g<<2 | (row&3)))*32 + na*2 + (row>>2)
    int xidx[2][2][4], widx[2][2][4];   // [m-half / n-half][k-half][j]
    #pragma unroll
    for (int half = 0; half < 2; ++half) {
        const int m = half * 64 + lrow;
        const int ma = m >> 4, r = m & 15;
        const int n = half * 64 + lrow;
        const int na = n >> 3, g = n & 7;
        #pragma unroll
        for (int kh = 0; kh < 2; ++kh) {
            #pragma unroll
            for (int j = 0; j < 4; ++j) {
                const int kl = lc + 16 * kh + j;
                const int ks = kl >> 3, c = kl & 7;
                xidx[half][kh][j] = ((ma * 4 + ks) * 32 + (((r & 7) << 2) | (c & 3))) * 4
                                    + (((c >> 2) << 1) | (r >> 3));
                const int row = kl & 7;
                widx[half][kh][j] = (ks * 32 + ((g << 2) | (row & 3))) * 32
                                    + na * 2 + (row >> 2);
            }
        }
    }

    // compute mapping
    const int w  = tid >> 5;      // warp 0..7
    const int wm = w & 3;         // m: rows wm*32..+31
    const int wn = w >> 2;        // n: cols wn*64..+63
    const int lane = tid & 31;

    float c[2][8][4];             // [m-atom][n-atom][frag]
    #pragma unroll
    for (int i = 0; i < 2; ++i)
        #pragma unroll
        for (int na = 0; na < 8; ++na)
            #pragma unroll
            for (int q = 0; q < 4; ++q) c[i][na][q] = 0.0f;

    // prologue: load tile 0, convert to tf32, commit to buf 0
    float4 st[8];   // xA0 xA1 xB0 xB1 wA0 wA1 wB0 wB1
    st[0] = *(const float4*)xp0;  st[1] = *(const float4*)(xp0 + 16);
    st[2] = *(const float4*)xp1;  st[3] = *(const float4*)(xp1 + 16);
    st[4] = *(const float4*)wp0;  st[5] = *(const float4*)(wp0 + 16);
    st[6] = *(const float4*)wp1;  st[7] = *(const float4*)(wp1 + 16);
    {
        #pragma unroll
        for (int half = 0; half < 2; ++half)
            #pragma unroll
            for (int kh = 0; kh < 2; ++kh) {
                const float* xv = (const float*)&st[half * 2 + kh];
                const float* wv = (const float*)&st[4 + half * 2 + kh];
                #pragma unroll
                for (int j = 0; j < 4; ++j) {
                    Xs[xidx[half][kh][j]] = to_tf32(xv[j]);
                    Ws[widx[half][kh][j]] = to_tf32(wv[j]);
                }
            }
    }
    __syncthreads();

    for (int t = 0; t < ntile; ++t) {
        const int buf = t & 1;
        const float* Xb = Xs + buf * XW;
        const float* Wb = Ws + buf * XW;

        const bool more = (t + 1 < ntile);
        if (more) {
            const size_t kt = (size_t)(t + 1) * FBK;
            st[0] = *(const float4*)(xp0 + kt);  st[1] = *(const float4*)(xp0 + kt + 16);
            st[2] = *(const float4*)(xp1 + kt);  st[3] = *(const float4*)(xp1 + kt + 16);
            st[4] = *(const float4*)(wp0 + kt);  st[5] = *(const float4*)(wp0 + kt + 16);
            st[6] = *(const float4*)(wp1 + kt);  st[7] = *(const float4*)(wp1 + kt + 16);
        }

        #pragma unroll
        for (int ks = 0; ks < 4; ++ks) {
            uint32_t af[2][4];
            #pragma unroll
            for (int i = 0; i < 2; ++i) {
                const int ma = wm * 2 + i;
                const float4 v = *(const float4*)&Xb[((ma * 4 + ks) * 32 + lane) * 4];
                const uint32_t* u = (const uint32_t*)&v;
                af[i][0] = u[0]; af[i][1] = u[1]; af[i][2] = u[2]; af[i][3] = u[3];
            }
            uint32_t bf[8][2];
            #pragma unroll
            for (int p = 0; p < 4; ++p) {
                const float4 v = *(const float4*)&Wb[(ks * 32 + lane) * 32
                                                     + (wn * 8 + p * 2) * 2];
                const uint32_t* u = (const uint32_t*)&v;
                bf[p * 2][0]     = u[0]; bf[p * 2][1]     = u[1];
                bf[p * 2 + 1][0] = u[2]; bf[p * 2 + 1][1] = u[3];
            }
            #pragma unroll
            for (int i = 0; i < 2; ++i)
                #pragma unroll
                for (int na = 0; na < 8; ++na)
                    mma_tf32(c[i][na], af[i], bf[na]);
        }

        if (more) {
            float* Xn = Xs + (buf ^ 1) * XW;
            float* Wn = Ws + (buf ^ 1) * XW;
            #pragma unroll
            for (int half = 0; half < 2; ++half)
                #pragma unroll
                for (int kh = 0; kh < 2; ++kh) {
                    const float* xv = (const float*)&st[half * 2 + kh];
                    const float* wv = (const float*)&st[4 + half * 2 + kh];
                    #pragma unroll
                    for (int j = 0; j < 4; ++j) {
                        Xn[xidx[half][kh][j]] = to_tf32(xv[j]);
                        Wn[widx[half][kh][j]] = to_tf32(wv[j]);
                    }
                }
        }
        __syncthreads();
    }

    // epilogue: c0/c1 -> (row, col..col+1), c2/c3 -> (row+8, ...)
    #pragma unroll
    for (int i = 0; i < 2; ++i) {
        const int row0 = m0 + wm * 32 + i * 16 + (lane >> 2);
        #pragma unroll
        for (int na = 0; na < 8; ++na) {
            const int col = n0 + wn * 64 + na * 8 + (lane & 3) * 2;
            float* p0 = g_partial + ((size_t)z * BATCH + row0) * 256 + col;
            float* p1 = p0 + 8 * 256;
            *(float2*)p0 = make_float2(c[i][na][0], c[i][na][1]);
            *(float2*)p1 = make_float2(c[i][na][2], c[i][na][3]);
        }
    }
}

// ------------------------------------------------------------------
// reduce: out = relu(sum_s partial + bias)
// ------------------------------------------------------------------
__global__ __launch_bounds__(256)
void reduce_kernel(const float* __restrict__ bias, float* __restrict__ out)
{
    const int g = blockIdx.x * 256 + threadIdx.x;
    const int m = g >> 6;
    const int nc = g & 63;
    float4 acc = ((const float4*)bias)[nc];
    #pragma unroll
    for (int ks = 0; ks < SPLITK; ++ks) {
        float4 p = ((const float4*)g_partial)[((size_t)ks * BATCH + m) * 64 + nc];
        acc.x += p.x; acc.y += p.y; acc.z += p.z; acc.w += p.w;
    }
    acc.x = fmaxf(acc.x, 0.0f); acc.y = fmaxf(acc.y, 0.0f);
    acc.z = fmaxf(acc.z, 0.0f); acc.w = fmaxf(acc.w, 0.0f);
    ((float4*)out)[(size_t)m * 64 + nc] = acc;
}

// ------------------------------------------------------------------
// launch
// ------------------------------------------------------------------
extern "C" void kernel_launch(void* const* d_in, const int* in_sizes, int n_in,
                              void* d_out, int out_size)
{
    const float* value = (const float*)d_in[0];
    const float* key_  = (const float*)d_in[1];
    const float* query = (const float*)d_in[2];
    const float* W_ff  = (const float*)d_in[4];
    const float* b_ff  = (const float*)d_in[5];

    float* out  = (float*)d_out;                 // [2048, 256]
    float* attn = out + (size_t)BATCH * 256;     // [2048, 64, 256]

    cudaFuncSetAttribute(attn_kernel,
                         cudaFuncAttributeMaxDynamicSharedMemorySize, ATTN_SMEM_BYTES);
    cudaFuncSetAttribute(ff2_kernel,
                         cudaFuncAttributeMaxDynamicSharedMemorySize, FF_SMEM_BYTES);

    attn_kernel<<<BATCH, 256, ATTN_SMEM_BYTES>>>(query, key_, value, attn);
    ff2_kernel<<<dim3(16, 2, SPLITK), 256, FF_SMEM_BYTES>>>(W_ff);
    reduce_kernel<<<512, 256>>>(b_ff, out);
}

// round 14
// speedup vs baseline: 1.1774x; 1.1774x over previous
#include <cuda_runtime.h>
#include <cstdint>
#include <math.h>

#define BATCH 2048
#define TT 64
#define EE 256
#define SCALE 0.125f
#define FK  16384
#define SPLITK 9            // uneven: 8 x 1824 + 1 x 1792

// ------------------------------------------------------------------
// scratch (static __device__ — no allocations allowed)
// ------------------------------------------------------------------
__device__ float g_x[BATCH * TT * EE];              // attn + query (134MB)
__device__ float g_partial[SPLITK * BATCH * 256];   // 18.9MB

// ------------------------------------------------------------------
// packed f32x2 helpers (FFMA2 — only reachable via PTX fma.rn.f32x2)
// ------------------------------------------------------------------
__device__ __forceinline__ void ffma2(uint64_t& d, uint64_t a, uint64_t b) {
    asm("fma.rn.f32x2 %0, %1, %2, %0;" : "+l"(d) : "l"(a), "l"(b));
}
__device__ __forceinline__ uint64_t dupf(float x) {
    uint64_t d; asm("mov.b64 %0, {%1, %1};" : "=l"(d) : "f"(x)); return d;
}
__device__ __forceinline__ void unpack2(uint64_t d, float& lo, float& hi) {
    asm("mov.b64 {%0, %1}, %2;" : "=f"(lo), "=f"(hi) : "l"(d));
}
__device__ __forceinline__ uint32_t smem_u32(const void* p) {
    uint32_t a;
    asm("{ .reg .u64 t; cvta.to.shared.u64 t, %1; cvt.u32.u64 %0, t; }" : "=r"(a) : "l"(p));
    return a;
}
#define CP_ASYNC16(dst, src) \
    asm volatile("cp.async.cg.shared.global [%0], [%1], 16;" :: "r"(dst), "l"(src) : "memory")
#define CP_COMMIT() \
    asm volatile("cp.async.commit_group;" ::: "memory")
#define CP_WAIT(n) \
    asm volatile("cp.async.wait_group %0;" :: "n"(n) : "memory")

// ------------------------------------------------------------------
// attention kernel: 256 threads, 2 CTAs/SM. (R10 version — best measured)
// ------------------------------------------------------------------
#define EC 64
#define NEC 4
#define KC 16
#define NKC 4
#define S_PITCH 65

#define OFF_QT 0
#define OFF_KT 8192
#define OFF_SS 16384
#define OFF_V  0
#define ATTN_SMEM_BYTES ((16384 + 4160) * 4)

__device__ __forceinline__ int qsw(int el, int q) {
    return el * 64 + ((((q) >> 2) ^ (el & 15)) << 2) + (q & 3);
}

__global__ __launch_bounds__(256, 2)
void attn_kernel(const float* __restrict__ Qg, const float* __restrict__ Kg,
                 const float* __restrict__ Vg, float* __restrict__ Ag)
{
    extern __shared__ float sm[];
    float* QT = sm + OFF_QT;
    float* KT = sm + OFF_KT;
    float* Ss = sm + OFF_SS;
    float* Vc = sm + OFF_V;

    const int tid = threadIdx.x;
    const int b   = blockIdx.x;
    const size_t base = (size_t)b * TT * EE;
    const float* qb = Qg + base;
    const float* kb = Kg + base;
    const float* vb = Vg + base;

    const int el = tid & 63;
    const int h  = tid >> 6;
    const int tx = tid & 15;
    const int ty = tid >> 4;

    {
        const float* qsrc = qb + (h * 16) * EE + el;
        const float* ksrc = kb + (h * 16) * EE + el;
        float qs[16], ks[16];
        #pragma unroll
        for (int r = 0; r < 16; ++r) {
            qs[r] = qsrc[r * EE];
            ks[r] = ksrc[r * EE];
        }
        #pragma unroll
        for (int r = 0; r < 16; ++r) {
            const int q = h * 16 + r;
            QT[qsw(el, q)] = qs[r];
            KT[qsw(el, q)] = ks[r];
        }
    }

    uint64_t accS[4][2];
    #pragma unroll
    for (int i = 0; i < 4; ++i) { accS[i][0] = 0ull; accS[i][1] = 0ull; }

    int cur = 0;
    float qs[16], ks[16];
    for (int ec = 0; ec < NEC; ++ec) {
        __syncthreads();
        if (ec < NEC - 1) {
            const float* qsrc = qb + (h * 16) * EE + (ec + 1) * EC + el;
            const float* ksrc = kb + (h * 16) * EE + (ec + 1) * EC + el;
            #pragma unroll
            for (int r = 0; r < 16; ++r) {
                qs[r] = qsrc[r * EE];
                ks[r] = ksrc[r * EE];
            }
        }
        const float* Qb = QT + cur * 4096;
        const float* Kb = KT + cur * 4096;
        #pragma unroll 16
        for (int e = 0; e < EC; ++e) {      // swizzle folds to immediates
            const int sw = e & 15;
            float4 qv = *(const float4*)&Qb[e * 64 + ((ty ^ sw) << 2)];
            float4 kv = *(const float4*)&Kb[e * 64 + ((tx ^ sw) << 2)];
            const uint64_t* kp = (const uint64_t*)&kv;
            ffma2(accS[0][0], dupf(qv.x), kp[0]);
            ffma2(accS[0][1], dupf(qv.x), kp[1]);
            ffma2(accS[1][0], dupf(qv.y), kp[0]);
            ffma2(accS[1][1], dupf(qv.y), kp[1]);
            ffma2(accS[2][0], dupf(qv.z), kp[0]);
            ffma2(accS[2][1], dupf(qv.z), kp[1]);
            ffma2(accS[3][0], dupf(qv.w), kp[0]);
            ffma2(accS[3][1], dupf(qv.w), kp[1]);
        }
        if (ec < NEC - 1) {
            float* Qn = QT + (cur ^ 1) * 4096;
            float* Kn = KT + (cur ^ 1) * 4096;
            #pragma unroll
            for (int r = 0; r < 16; ++r) {
                const int q = h * 16 + r;
                Qn[qsw(el, q)] = qs[r];
                Kn[qsw(el, q)] = ks[r];
            }
            cur ^= 1;
        }
    }

    #pragma unroll
    for (int i = 0; i < 4; ++i) {
        float s0, s1, s2, s3;
        unpack2(accS[i][0], s0, s1);
        unpack2(accS[i][1], s2, s3);
        float* sr = &Ss[(ty * 4 + i) * S_PITCH + tx * 4];
        sr[0] = s0; sr[1] = s1; sr[2] = s2; sr[3] = s3;
    }
    __syncthreads();

    const uint32_t vsm = smem_u32(Vc);
    #pragma unroll
    for (int j = 0; j < 4; ++j) {
        const int f4 = j * 256 + tid;
        CP_ASYNC16(vsm + f4 * 16, (const float4*)vb + f4);
    }
    CP_COMMIT();

    const int warp = tid >> 5, lane = tid & 31;
    #pragma unroll
    for (int rr = 0; rr < 8; ++rr) {
        const int r = warp * 8 + rr;
        float v1 = Ss[r * S_PITCH + lane]      * SCALE;
        float v2 = Ss[r * S_PITCH + lane + 32] * SCALE;
        float m = fmaxf(v1, v2);
        #pragma unroll
        for (int o = 16; o > 0; o >>= 1)
            m = fmaxf(m, __shfl_xor_sync(0xffffffffu, m, o));
        float e1 = expf(v1 - m);
        float e2 = expf(v2 - m);
        float s = e1 + e2;
        #pragma unroll
        for (int o = 16; o > 0; o >>= 1)
            s += __shfl_xor_sync(0xffffffffu, s, o);
        float inv = 1.0f / s;
        Ss[r * S_PITCH + lane]      = e1 * inv;
        Ss[r * S_PITCH + lane + 32] = e2 * inv;
    }

    uint64_t accA[4][4][2];
    #pragma unroll
    for (int i = 0; i < 4; ++i)
        #pragma unroll
        for (int eb = 0; eb < 4; ++eb) { accA[i][eb][0] = 0ull; accA[i][eb][1] = 0ull; }

    for (int kc = 0; kc < NKC; ++kc) {
        if (kc < NKC - 1) {
            const uint32_t dst = vsm + (((kc + 1) & 1) * 4096) * 4;
            #pragma unroll
            for (int j = 0; j < 4; ++j) {
                const int f4 = j * 256 + tid;
                CP_ASYNC16(dst + f4 * 16, (const float4*)vb + (kc + 1) * 1024 + f4);
            }
            CP_COMMIT();
            CP_WAIT(1);
        } else {
            CP_WAIT(0);
        }
        __syncthreads();
        const float* Vb = Vc + (kc & 1) * 4096;
        #pragma unroll 2
        for (int kl = 0; kl < KC; ++kl) {
            const int kg = kc * KC + kl;
            float4 v0 = *(const float4*)&Vb[kl * 256 + tx * 4];
            float4 v1 = *(const float4*)&Vb[kl * 256 + 64 + tx * 4];
            float4 v2 = *(const float4*)&Vb[kl * 256 + 128 + tx * 4];
            float4 v3 = *(const float4*)&Vb[kl * 256 + 192 + tx * 4];
            uint64_t vp[4][2];
            { const uint64_t* u = (const uint64_t*)&v0; vp[0][0] = u[0]; vp[0][1] = u[1]; }
            { const uint64_t* u = (const uint64_t*)&v1; vp[1][0] = u[0]; vp[1][1] = u[1]; }
            { const uint64_t* u = (const uint64_t*)&v2; vp[2][0] = u[0]; vp[2][1] = u[1]; }
            { const uint64_t* u = (const uint64_t*)&v3; vp[3][0] = u[0]; vp[3][1] = u[1]; }
            #pragma unroll
            for (int i = 0; i < 4; ++i) {
                uint64_t sd = dupf(Ss[(ty * 4 + i) * S_PITCH + kg]);
                #pragma unroll
                for (int eb = 0; eb < 4; ++eb) {
                    ffma2(accA[i][eb][0], sd, vp[eb][0]);
                    ffma2(accA[i][eb][1], sd, vp[eb][1]);
                }
            }
        }
        __syncthreads();
    }

    float* ab = Ag + base;
    float* xb = g_x + base;
    #pragma unroll
    for (int i = 0; i < 4; ++i) {
        const int qrow = ty * 4 + i;
        #pragma unroll
        for (int eb = 0; eb < 4; ++eb) {
            const int e0 = eb * 64 + tx * 4;
            float4 o;
            unpack2(accA[i][eb][0], o.x, o.y);
            unpack2(accA[i][eb][1], o.z, o.w);
            float4 q = *(const float4*)&qb[qrow * EE + e0];
            float4 x = make_float4(o.x + q.x, o.y + q.y, o.z + q.z, o.w + q.w);
            *(float4*)&ab[qrow * EE + e0] = o;
            *(float4*)&xb[qrow * EE + e0] = x;
        }
    }
}

// ------------------------------------------------------------------
// FF GEMM: partial[s][m][n] = g_x[m, s-range] @ W^T   (FFMA2 SIMT)
// acc packed over k (even/odd): both FFMA2 operands are natural k-pairs
// -> ZERO dup-MOVs in the hot loop. Smem k-pair-major uint64 layouts.
// 256 threads, BM=128 BN=64 BK=32, thread tile 8m x 4n (n = tx+16j).
// grid (16, 4, 9) = 576 CTAs = 2 near-full waves.
// ------------------------------------------------------------------
#define FBM 128
#define FBN 64
#define FBK 32
#define XPITCH 130                   // uint64 per k-pair row (128 m + pad)
#define WPITCH 66                    // 64 n + pad
#define XBUFW (16 * XPITCH)          // 2080 u64
#define WBUFW (16 * WPITCH)          // 1056 u64
#define FF_SMEM_BYTES ((2 * XBUFW + 2 * WBUFW) * 8)   // 50176 B
#define KTPS 57                      // splits 0..7: 57 tiles; split 8: 56

__global__ __launch_bounds__(256, 2)
void ff2_kernel(const float* __restrict__ Wg)
{
    extern __shared__ uint64_t usm[];
    uint64_t* Xs = usm;              // [2][16][XPITCH]
    uint64_t* Ws = usm + 2 * XBUFW;  // [2][16][WPITCH]

    const int tid = threadIdx.x;
    const int m0 = blockIdx.x * FBM;
    const int n0 = blockIdx.y * FBN;
    const int z  = blockIdx.z;
    const size_t kbase = (size_t)z * (KTPS * FBK);
    const int ntile = (z == SPLITK - 1) ? 56 : KTPS;

    const int lrow = tid >> 2;          // 0..63
    const int lc   = (tid & 3) * 4;     // 0,4,8,12
    const int kp0  = lc >> 1;           // 0,2,4,6
    const float* xp0 = g_x + (size_t)(m0 + lrow) * FK + kbase + lc;
    const float* xp1 = g_x + (size_t)(m0 + 64 + lrow) * FK + kbase + lc;
    const float* wpt = Wg  + (size_t)(n0 + lrow) * FK + kbase + lc;

    const int tx = tid & 15;    // n = tx + 16j, j=0..3
    const int ty = tid >> 4;    // m rows ty*8..+7 (16 lanes share ty -> broadcast)

    uint64_t acc[8][4];         // [m][j]; each = (sum even k, sum odd k)
    #pragma unroll
    for (int m = 0; m < 8; ++m)
        #pragma unroll
        for (int j = 0; j < 4; ++j) acc[m][j] = 0ull;

    // staging registers
    float4 xA0, xA1, xB0, xB1, wA0, wA1;

#define FF_COMMIT(BUF) do {                                                   \
    uint64_t* X = Xs + (BUF) * XBUFW;                                         \
    uint64_t* W = Ws + (BUF) * WBUFW;                                         \
    const uint64_t* p;                                                        \
    p = (const uint64_t*)&xA0;                                                \
    X[(kp0 + 0) * XPITCH + lrow] = p[0];                                      \
    X[(kp0 + 1) * XPITCH + lrow] = p[1];                                      \
    p = (const uint64_t*)&xA1;                                                \
    X[(kp0 + 8) * XPITCH + lrow] = p[0];                                      \
    X[(kp0 + 9) * XPITCH + lrow] = p[1];                                      \
    p = (const uint64_t*)&xB0;                                                \
    X[(kp0 + 0) * XPITCH + lrow + 64] = p[0];                                 \
    X[(kp0 + 1) * XPITCH + lrow + 64] = p[1];                                 \
    p = (const uint64_t*)&xB1;                                                \
    X[(kp0 + 8) * XPITCH + lrow + 64] = p[0];                                 \
    X[(kp0 + 9) * XPITCH + lrow + 64] = p[1];                                 \
    p = (const uint64_t*)&wA0;                                                \
    W[(kp0 + 0) * WPITCH + lrow] = p[0];                                      \
    W[(kp0 + 1) * WPITCH + lrow] = p[1];                                      \
    p = (const uint64_t*)&wA1;                                                \
    W[(kp0 + 8) * WPITCH + lrow] = p[0];                                      \
    W[(kp0 + 9) * WPITCH + lrow] = p[1];                                      \
} while (0)

    // prologue: load + commit tile 0
    xA0 = *(const float4*)xp0;  xA1 = *(const float4*)(xp0 + 16);
    xB0 = *(const float4*)xp1;  xB1 = *(const float4*)(xp1 + 16);
    wA0 = *(const float4*)wpt;  wA1 = *(const float4*)(wpt + 16);
    FF_COMMIT(0);
    __syncthreads();

    for (int t = 0; t < ntile; ++t) {
        const int buf = t & 1;
        const uint64_t* Xb = Xs + buf * XBUFW;
        const uint64_t* Wb = Ws + buf * WBUFW;

        const bool more = (t + 1 < ntile);
        if (more) {
            const size_t kt = (size_t)(t + 1) * FBK;
            xA0 = *(const float4*)(xp0 + kt);  xA1 = *(const float4*)(xp0 + kt + 16);
            xB0 = *(const float4*)(xp1 + kt);  xB1 = *(const float4*)(xp1 + kt + 16);
            wA0 = *(const float4*)(wpt + kt);  wA1 = *(const float4*)(wpt + kt + 16);
        }

        #pragma unroll
        for (int kp = 0; kp < 16; ++kp) {
            const uint64_t* xr = Xb + kp * XPITCH + ty * 8;
            uint64_t a[8];
            #pragma unroll
            for (int i = 0; i < 4; ++i) {       // 4x LDS.128 (broadcast)
                longlong2 v = *(const longlong2*)(xr + 2 * i);
                a[2 * i]     = (uint64_t)v.x;
                a[2 * i + 1] = (uint64_t)v.y;
            }
            const uint64_t* wr = Wb + kp * WPITCH + tx;
            uint64_t b0 = wr[0], b1 = wr[16], b2 = wr[32], b3 = wr[48];  // LDS.64, conflict-free
            #pragma unroll
            for (int m = 0; m < 8; ++m) {
                ffma2(acc[m][0], a[m], b0);
                ffma2(acc[m][1], a[m], b1);
                ffma2(acc[m][2], a[m], b2);
                ffma2(acc[m][3], a[m], b3);
            }
        }

        if (more) FF_COMMIT(buf ^ 1);
        __syncthreads();
    }

    // epilogue: fold even/odd sums; thread owns cols n0 + tx + 16j
    #pragma unroll
    for (int m = 0; m < 8; ++m) {
        const int row = m0 + ty * 8 + m;
        float* pr = g_partial + ((size_t)z * BATCH + row) * 256 + n0 + tx;
        #pragma unroll
        for (int j = 0; j < 4; ++j) {
            float lo, hi;
            unpack2(acc[m][j], lo, hi);
            pr[16 * j] = lo + hi;
        }
    }
#undef FF_COMMIT
}

// ------------------------------------------------------------------
// reduce: out = relu(sum_s partial + bias)
// ------------------------------------------------------------------
__global__ __launch_bounds__(256)
void reduce_kernel(const float* __restrict__ bias, float* __restrict__ out)
{
    const int g = blockIdx.x * 256 + threadIdx.x;
    const int m = g >> 6;
    const int nc = g & 63;
    float4 acc = ((const float4*)bias)[nc];
    #pragma unroll
    for (int ks = 0; ks < SPLITK; ++ks) {
        float4 p = ((const float4*)g_partial)[((size_t)ks * BATCH + m) * 64 + nc];
        acc.x += p.x; acc.y += p.y; acc.z += p.z; acc.w += p.w;
    }
    acc.x = fmaxf(acc.x, 0.0f); acc.y = fmaxf(acc.y, 0.0f);
    acc.z = fmaxf(acc.z, 0.0f); acc.w = fmaxf(acc.w, 0.0f);
    ((float4*)out)[(size_t)m * 64 + nc] = acc;
}

// ------------------------------------------------------------------
// launch
// ------------------------------------------------------------------
extern "C" void kernel_launch(void* const* d_in, const int* in_sizes, int n_in,
                              void* d_out, int out_size)
{
    const float* value = (const float*)d_in[0];
    const float* key_  = (const float*)d_in[1];
    const float* query = (const float*)d_in[2];
    const float* W_ff  = (const float*)d_in[4];
    const float* b_ff  = (const float*)d_in[5];

    float* out  = (float*)d_out;                 // [2048, 256]
    float* attn = out + (size_t)BATCH * 256;     // [2048, 64, 256]

    cudaFuncSetAttribute(attn_kernel,
                         cudaFuncAttributeMaxDynamicSharedMemorySize, ATTN_SMEM_BYTES);
    cudaFuncSetAttribute(ff2_kernel,
                         cudaFuncAttributeMaxDynamicSharedMemorySize, FF_SMEM_BYTES);

    attn_kernel<<<BATCH, 256, ATTN_SMEM_BYTES>>>(query, key_, value, attn);
    ff2_kernel<<<dim3(16, 4, SPLITK), 256, FF_SMEM_BYTES>>>(W_ff);
    reduce_kernel<<<512, 256>>>(b_ff, out);
}